// round 6
// baseline (speedup 1.0000x reference)
#include <cuda_runtime.h>
#include <math.h>

// ---------------------------------------------------------------------------
// x: (8,3,1024,1024) fp32. 16x16 DCT blocks -> 98304 blocks total.
// f32x2-packed, single fused kernel. CTA = 256 threads = 32 blocks
// (16 rows x 512 cols). Last CTA (release/acquire ticket) writes the scalar.
// ---------------------------------------------------------------------------

#define GRID_DIM 3072
#define N_BLOCKS_TOTAL 98304
#define CST 34                 // col stride in smem (floats), ≡2 mod 32
#define IST 546                // row stride in smem (floats), ≡2 mod 32, even
#define SMEMF (16 * IST)       // 8736 floats = 34.9 KB

// Compile-time cos via constexpr Taylor (folds DCT coeffs to compile-time consts)
constexpr double PI_D = 3.14159265358979323846;
__host__ __device__ constexpr double ccos(double x) {
    while (x > PI_D)  x -= 2.0 * PI_D;
    while (x < -PI_D) x += 2.0 * PI_D;
    double x2 = x * x;
    double term = 1.0, sum = 1.0;
    for (int i = 1; i <= 16; ++i) {
        term *= -x2 / double((2 * i - 1) * (2 * i));
        sum += term;
    }
    return sum;
}
__host__ __device__ constexpr float CN(int n) {  // cos(n*pi/32)
    return (float)ccos(n * PI_D / 32.0);
}

// Precomputed zigzag -> smem float-offset table (r*IST + c*CST), u16 each.
struct OffT { alignas(16) unsigned short v[128]; };
__host__ __device__ constexpr OffT make_off() {
    OffT t{};
    const int zz[128] = {
        135, 150, 165, 180, 195, 210, 225, 240, 241, 226, 211, 196, 181, 166, 151,
        136, 121, 106, 91, 76, 61, 46, 31, 47, 62, 77, 92, 107, 122, 137, 152, 167,
        182, 197, 212, 227, 242, 243, 228, 213, 198, 183, 168, 153, 138, 123, 108,
        93, 78, 63, 79, 94, 109, 124, 139, 154, 169, 184, 199, 214, 229, 244, 245,
        230, 215, 200, 185, 170, 155, 140, 125, 110, 95, 111, 126, 141, 156, 171,
        186, 201, 216, 231, 246, 247, 232, 217, 202, 187, 172, 157, 142, 127, 143,
        158, 173, 188, 203, 218, 233, 248, 249, 234, 219, 204, 189, 174, 159, 175,
        190, 205, 220, 235, 250, 251, 236, 221, 206, 191, 207, 222, 237, 252, 253,
        238, 223, 239, 254, 255};
    for (int e = 0; e < 128; ++e) {
        const int id = zz[e];
        t.v[e] = (unsigned short)((id >> 4) * IST + (id & 15) * CST);
    }
    return t;
}
__device__ const OffT g_off = make_off();

__device__ double g_acc = 0.0;
__device__ unsigned int g_ticket = 0u;

// ---------------- packed f32x2 helpers (Blackwell sm_100+) ----------------
using u64 = unsigned long long;
__device__ __forceinline__ u64 pk2(float v) {
    u64 r; asm("mov.b64 %0,{%1,%1};" : "=l"(r) : "f"(v)); return r;
}
__device__ __forceinline__ u64 addf2(u64 a, u64 b) {
    u64 r; asm("add.rn.f32x2 %0,%1,%2;" : "=l"(r) : "l"(a), "l"(b)); return r;
}
__device__ __forceinline__ u64 mulf2(u64 a, u64 b) {
    u64 r; asm("mul.rn.f32x2 %0,%1,%2;" : "=l"(r) : "l"(a), "l"(b)); return r;
}
__device__ __forceinline__ u64 fmaf2(u64 a, u64 b, u64 c) {
    u64 r; asm("fma.rn.f32x2 %0,%1,%2,%3;" : "=l"(r) : "l"(a), "l"(b), "l"(c)); return r;
}
__device__ __forceinline__ u64 subf2(u64 a, u64 b) {  // a - b
    return fmaf2(b, pk2(-1.0f), a);
}
__device__ __forceinline__ float lo2(u64 a) {
    float f; asm("{ .reg .f32 t; mov.b64 {%0, t}, %1; }" : "=f"(f) : "l"(a)); return f;
}
__device__ __forceinline__ float hi2(u64 a) {
    float f; asm("{ .reg .f32 t; mov.b64 {t, %0}, %1; }" : "=f"(f) : "l"(a)); return f;
}

// 16-point DCT-II, packed 2-wide. o[i] = sum_k x[k]*cos((2k+1)*i*pi/32)
__device__ __forceinline__ void dct16p(const u64 x[16], u64 o[16]) {
    u64 s[8], d[8];
#pragma unroll
    for (int k = 0; k < 8; ++k) {
        s[k] = addf2(x[k], x[15 - k]);
        d[k] = subf2(x[k], x[15 - k]);
    }
#pragma unroll
    for (int i = 1; i < 16; i += 2) {          // odd outputs: 8-tap on d
        u64 acc = mulf2(d[0], pk2(CN(i)));
#pragma unroll
        for (int k = 1; k < 8; ++k) acc = fmaf2(d[k], pk2(CN((2 * k + 1) * i)), acc);
        o[i] = acc;
    }
    u64 s2[4], d2[4];
#pragma unroll
    for (int k = 0; k < 4; ++k) {
        s2[k] = addf2(s[k], s[7 - k]);
        d2[k] = subf2(s[k], s[7 - k]);
    }
#pragma unroll
    for (int m = 1; m < 8; m += 2) {           // o[2m]: 4-tap on d2
        u64 acc = mulf2(d2[0], pk2(CN(2 * m)));
#pragma unroll
        for (int k = 1; k < 4; ++k) acc = fmaf2(d2[k], pk2(CN(2 * (2 * k + 1) * m)), acc);
        o[2 * m] = acc;
    }
    u64 s3_0 = addf2(s2[0], s2[3]), s3_1 = addf2(s2[1], s2[2]);
    u64 d3_0 = subf2(s2[0], s2[3]), d3_1 = subf2(s2[1], s2[2]);
    o[4]  = fmaf2(d3_1, pk2(CN(12)), mulf2(d3_0, pk2(CN(4))));
    o[12] = fmaf2(d3_1, pk2(CN(36)), mulf2(d3_0, pk2(CN(12))));
    o[0]  = addf2(s3_0, s3_1);
    o[8]  = mulf2(subf2(s3_0, s3_1), pk2(CN(8)));
}

__global__ __launch_bounds__(256, 2) void ube_kernel(const float* __restrict__ in,
                                                     float* __restrict__ out) {
    __shared__ float sw[SMEMF];
    __shared__ float spart[32];

    const int tid = threadIdx.x;

    // strip decode: 24 images x 128 strips (64 block-rows x 2 half-rows)
    const int s    = blockIdx.x;
    const int img  = s >> 7;
    const int rem  = s & 127;
    const int brow = rem >> 1;
    const int scol = rem & 1;
    const float* p = in + (size_t)img * (1024u * 1024u) + brow * (16 * 1024) +
                     scol * 512 + 2 * tid;

    // ---- stage 1: packed column DCT (2 adjacent columns per thread) ----
    {
        u64 x[16];
#pragma unroll
        for (int r = 0; r < 16; ++r)
            x[r] = *reinterpret_cast<const u64*>(p + r * 1024);
        u64 o[16];
        dct16p(x, o);
        // scatter scalar halves into [row][col][blk] layout
        const int blk = tid >> 3;        // 0..31
        const int cp  = tid & 7;         // column-pair 0..7
        const int base = (2 * cp) * CST + blk;
#pragma unroll
        for (int i = 1; i < 16; ++i) {
            sw[i * IST + base]       = lo2(o[i]);
            sw[i * IST + base + CST] = hi2(o[i]);
        }
    }
    __syncthreads();

    // ---- stage 2: packed row DCT (2 blocks per thread, same row) ----
    {
        const int g = tid >> 4;          // block pair 0..15 (blocks 2g, 2g+1)
        const int r = tid & 15;          // row 0..15 (row 0 result unused)
        u64 w[16];
        const int rb = r * IST + 2 * g;
#pragma unroll
        for (int c = 0; c < 16; ++c)
            w[c] = *reinterpret_cast<const u64*>(&sw[rb + c * CST]);
        u64 cf[16];
        dct16p(w, cf);
        // in-place writeback: [r][j][2g..2g+1] — only this thread touches these
#pragma unroll
        for (int j = 0; j < 16; ++j)
            *reinterpret_cast<u64*>(&sw[rb + j * CST]) = cf[j];
    }
    __syncthreads();

    // ---- balanced zigzag entropy: 8 threads/block x 16 entries ----
    {
        const int B   = tid >> 3;        // block 0..31
        const int sub = tid & 7;         // 0..7
        const uint4* tp = reinterpret_cast<const uint4*>(g_off.v);
        const uint4 w0 = tp[sub * 2], w1 = tp[sub * 2 + 1];
        const unsigned sh[8] = {w0.x, w0.y, w0.z, w0.w, w1.x, w1.y, w1.z, w1.w};

        float v[16];
#pragma unroll
        for (int e = 0; e < 16; ++e) {
            const unsigned off = (sh[e >> 1] >> ((e & 1) * 16)) & 0xFFFFu;
            v[e] = sw[off + B] * 0.17677669529663689f;   // SCALE*n (r>=1 rows)
        }
        if (sub == 0) v[7] *= 0.70710678118654752f;      // the single c==0 entry

        // per-block mean over 128 (reduce across 8-lane group)
        float sum = 0.0f;
#pragma unroll
        for (int e = 0; e < 16; ++e) sum += v[e];
#pragma unroll
        for (int m = 4; m >= 1; m >>= 1) sum += __shfl_xor_sync(0xffffffffu, sum, m);
        const float mean = sum * (1.0f / 128.0f);

        float sa = 0.0f, sq = 0.0f, sl = 0.0f;
#pragma unroll
        for (int e = 0; e < 16; ++e) {
            const float f = (v[e] < mean) ? 0.0f : v[e];
            const float a = fabsf(f) + 1e-12f;
            sa += a;
            sq  = fmaf(a, a, sq);
            sl  = fmaf(a, __log2f(a), sl);
        }
#pragma unroll
        for (int m = 4; m >= 1; m >>= 1) {
            sa += __shfl_xor_sync(0xffffffffu, sa, m);
            sq += __shfl_xor_sync(0xffffffffu, sq, m);
            sl += __shfl_xor_sync(0xffffffffu, sl, m);
        }
        if (sub == 0) {
            const float nrm = fmaxf(sqrtf(sq), 1e-12f);
            spart[B] = (__log2f(nrm) * sa - sl) / nrm;
        }
    }
    __syncthreads();

    // ---- CTA aggregate + last-CTA finalize (release/acquire ticket) ----
    if (tid == 0) {
        float c0 = 0.0f;
#pragma unroll
        for (int b = 0; b < 32; ++b) c0 += spart[b];
        atomicAdd(&g_acc, (double)c0);              // relaxed device atomic (L2)
        unsigned t;
        asm volatile("atom.add.release.gpu.global.u32 %0, [%1], 1;"
                     : "=r"(t) : "l"(&g_ticket) : "memory");
        if (t == (unsigned)(GRID_DIM - 1)) {        // last CTA: all adds visible
            double v;
            asm volatile("ld.acquire.gpu.global.f64 %0, [%1];"
                         : "=d"(v) : "l"(&g_acc) : "memory");
            out[0] = (float)(v * (1.0 / (double)N_BLOCKS_TOTAL));
            g_acc = 0.0;                            // reset for next replay
            asm volatile("st.release.gpu.global.u32 [%0], 0;"
                         :: "l"(&g_ticket) : "memory");
        }
    }
}

extern "C" void kernel_launch(void* const* d_in, const int* in_sizes, int n_in,
                              void* d_out, int out_size) {
    const float* x = (const float*)d_in[0];
    float* out = (float*)d_out;
    ube_kernel<<<GRID_DIM, 256>>>(x, out);
}

// round 7
// speedup vs baseline: 1.0849x; 1.0849x over previous
#include <cuda_runtime.h>
#include <math.h>

// ---------------------------------------------------------------------------
// x: (8,3,1024,1024) fp32. 16x16 DCT blocks -> 98304 blocks total.
// f32x2-packed, single fused kernel, fully WARP-LOCAL pipeline:
//   warp w owns blocks 4w..4w+3 through stage1 / stage2 / entropy, so the
//   stage barriers are __syncwarp (no CTA-wide coupling).
// CTA = 256 threads = 32 blocks (16 rows x 512 cols). Grid = 3072.
// Last CTA (release/acquire ticket) writes the scalar output.
// ---------------------------------------------------------------------------

#define GRID_DIM 3072
#define N_BLOCKS_TOTAL 98304
#define CST 34                 // col stride in smem (floats), ≡2 mod 32
#define IST 546                // row stride in smem (floats), ≡2 mod 32, even
#define SMEMF (16 * IST)       // 8736 floats = 34.9 KB

// Compile-time cos via constexpr Taylor (folds DCT coeffs to compile-time consts)
constexpr double PI_D = 3.14159265358979323846;
__host__ __device__ constexpr double ccos(double x) {
    while (x > PI_D)  x -= 2.0 * PI_D;
    while (x < -PI_D) x += 2.0 * PI_D;
    double x2 = x * x;
    double term = 1.0, sum = 1.0;
    for (int i = 1; i <= 16; ++i) {
        term *= -x2 / double((2 * i - 1) * (2 * i));
        sum += term;
    }
    return sum;
}
__host__ __device__ constexpr float CN(int n) {  // cos(n*pi/32)
    return (float)ccos(n * PI_D / 32.0);
}

// Precomputed zigzag -> smem float-offset table (r*IST + c*CST), u16 each.
struct OffT { alignas(16) unsigned short v[128]; };
__host__ __device__ constexpr OffT make_off() {
    OffT t{};
    const int zz[128] = {
        135, 150, 165, 180, 195, 210, 225, 240, 241, 226, 211, 196, 181, 166, 151,
        136, 121, 106, 91, 76, 61, 46, 31, 47, 62, 77, 92, 107, 122, 137, 152, 167,
        182, 197, 212, 227, 242, 243, 228, 213, 198, 183, 168, 153, 138, 123, 108,
        93, 78, 63, 79, 94, 109, 124, 139, 154, 169, 184, 199, 214, 229, 244, 245,
        230, 215, 200, 185, 170, 155, 140, 125, 110, 95, 111, 126, 141, 156, 171,
        186, 201, 216, 231, 246, 247, 232, 217, 202, 187, 172, 157, 142, 127, 143,
        158, 173, 188, 203, 218, 233, 248, 249, 234, 219, 204, 189, 174, 159, 175,
        190, 205, 220, 235, 250, 251, 236, 221, 206, 191, 207, 222, 237, 252, 253,
        238, 223, 239, 254, 255};
    for (int e = 0; e < 128; ++e) {
        const int id = zz[e];
        t.v[e] = (unsigned short)((id >> 4) * IST + (id & 15) * CST);
    }
    return t;
}
__device__ const OffT g_off = make_off();

__device__ double g_acc = 0.0;
__device__ unsigned int g_ticket = 0u;

// ---------------- packed f32x2 helpers (Blackwell sm_100+) ----------------
using u64 = unsigned long long;
__device__ __forceinline__ u64 pk2(float v) {
    u64 r; asm("mov.b64 %0,{%1,%1};" : "=l"(r) : "f"(v)); return r;
}
__device__ __forceinline__ u64 addf2(u64 a, u64 b) {
    u64 r; asm("add.rn.f32x2 %0,%1,%2;" : "=l"(r) : "l"(a), "l"(b)); return r;
}
__device__ __forceinline__ u64 mulf2(u64 a, u64 b) {
    u64 r; asm("mul.rn.f32x2 %0,%1,%2;" : "=l"(r) : "l"(a), "l"(b)); return r;
}
__device__ __forceinline__ u64 fmaf2(u64 a, u64 b, u64 c) {
    u64 r; asm("fma.rn.f32x2 %0,%1,%2,%3;" : "=l"(r) : "l"(a), "l"(b), "l"(c)); return r;
}
__device__ __forceinline__ u64 subf2(u64 a, u64 b) {  // a - b
    return fmaf2(b, pk2(-1.0f), a);
}
__device__ __forceinline__ float lo2(u64 a) {
    float f; asm("{ .reg .f32 t; mov.b64 {%0, t}, %1; }" : "=f"(f) : "l"(a)); return f;
}
__device__ __forceinline__ float hi2(u64 a) {
    float f; asm("{ .reg .f32 t; mov.b64 {t, %0}, %1; }" : "=f"(f) : "l"(a)); return f;
}

// 16-point DCT-II, packed 2-wide. o[i] = sum_k x[k]*cos((2k+1)*i*pi/32)
__device__ __forceinline__ void dct16p(const u64 x[16], u64 o[16]) {
    u64 s[8], d[8];
#pragma unroll
    for (int k = 0; k < 8; ++k) {
        s[k] = addf2(x[k], x[15 - k]);
        d[k] = subf2(x[k], x[15 - k]);
    }
#pragma unroll
    for (int i = 1; i < 16; i += 2) {          // odd outputs: 8-tap on d
        u64 acc = mulf2(d[0], pk2(CN(i)));
#pragma unroll
        for (int k = 1; k < 8; ++k) acc = fmaf2(d[k], pk2(CN((2 * k + 1) * i)), acc);
        o[i] = acc;
    }
    u64 s2[4], d2[4];
#pragma unroll
    for (int k = 0; k < 4; ++k) {
        s2[k] = addf2(s[k], s[7 - k]);
        d2[k] = subf2(s[k], s[7 - k]);
    }
#pragma unroll
    for (int m = 1; m < 8; m += 2) {           // o[2m]: 4-tap on d2
        u64 acc = mulf2(d2[0], pk2(CN(2 * m)));
#pragma unroll
        for (int k = 1; k < 4; ++k) acc = fmaf2(d2[k], pk2(CN(2 * (2 * k + 1) * m)), acc);
        o[2 * m] = acc;
    }
    u64 s3_0 = addf2(s2[0], s2[3]), s3_1 = addf2(s2[1], s2[2]);
    u64 d3_0 = subf2(s2[0], s2[3]), d3_1 = subf2(s2[1], s2[2]);
    o[4]  = fmaf2(d3_1, pk2(CN(12)), mulf2(d3_0, pk2(CN(4))));
    o[12] = fmaf2(d3_1, pk2(CN(36)), mulf2(d3_0, pk2(CN(12))));
    o[0]  = addf2(s3_0, s3_1);
    o[8]  = mulf2(subf2(s3_0, s3_1), pk2(CN(8)));
}

__global__ __launch_bounds__(256, 2) void ube_kernel(const float* __restrict__ in,
                                                     float* __restrict__ out) {
    __shared__ float sw[SMEMF];
    __shared__ float spart[32];

    const int tid = threadIdx.x;

    // strip decode: 24 images x 128 strips (64 block-rows x 2 half-rows)
    const int s    = blockIdx.x;
    const int img  = s >> 7;
    const int rem  = s & 127;
    const int brow = rem >> 1;
    const int scol = rem & 1;
    const float* p = in + (size_t)img * (1024u * 1024u) + brow * (16 * 1024) +
                     scol * 512 + 2 * tid;

    // ---- stage 1: packed column DCT (2 adjacent columns per thread) ----
    // warp w writes only blocks 4w..4w+3 (blk = tid>>3)
    {
        u64 x[16];
#pragma unroll
        for (int r = 0; r < 16; ++r)
            x[r] = *reinterpret_cast<const u64*>(p + r * 1024);
        u64 o[16];
        dct16p(x, o);
        const int blk = tid >> 3;        // 0..31
        const int cp  = tid & 7;         // column-pair 0..7
        const int base = (2 * cp) * CST + blk;
#pragma unroll
        for (int i = 1; i < 16; ++i) {
            sw[i * IST + base]       = lo2(o[i]);
            sw[i * IST + base + CST] = hi2(o[i]);
        }
    }
    __syncwarp();   // stage-1 -> stage-2 dependency is warp-local

    // ---- stage 2: packed row DCT (2 blocks per thread, same row) ----
    // warp w reads/writes blocks 4w..4w+3 (g = tid>>4 -> 2w, 2w+1)
    {
        const int g = tid >> 4;          // block pair (blocks 2g, 2g+1)
        const int r = tid & 15;          // row (row 0 result unused)
        u64 w[16];
        const int rb = r * IST + 2 * g;
#pragma unroll
        for (int c = 0; c < 16; ++c)
            w[c] = *reinterpret_cast<const u64*>(&sw[rb + c * CST]);
        u64 cf[16];
        dct16p(w, cf);
#pragma unroll
        for (int j = 0; j < 16; ++j)
            *reinterpret_cast<u64*>(&sw[rb + j * CST]) = cf[j];
    }
    __syncwarp();   // stage-2 -> gather dependency is warp-local

    // ---- balanced zigzag entropy: 8 threads/block x 16 entries ----
    // warp w reads blocks 4w..4w+3 (B = tid>>3)
    {
        const int B   = tid >> 3;        // block 0..31
        const int sub = tid & 7;         // 0..7
        const uint4* tp = reinterpret_cast<const uint4*>(g_off.v);
        const uint4 w0 = tp[sub * 2], w1 = tp[sub * 2 + 1];
        const unsigned sh[8] = {w0.x, w0.y, w0.z, w0.w, w1.x, w1.y, w1.z, w1.w};

        float v[16];
#pragma unroll
        for (int e = 0; e < 16; ++e) {
            const unsigned off = (sh[e >> 1] >> ((e & 1) * 16)) & 0xFFFFu;
            v[e] = sw[off + B] * 0.17677669529663689f;   // SCALE*n (r>=1 rows)
        }
        if (sub == 0) v[7] *= 0.70710678118654752f;      // the single c==0 entry

        // per-block mean over 128 (reduce across 8-lane group)
        float sum = 0.0f;
#pragma unroll
        for (int e = 0; e < 16; ++e) sum += v[e];
#pragma unroll
        for (int m = 4; m >= 1; m >>= 1) sum += __shfl_xor_sync(0xffffffffu, sum, m);
        const float mean = sum * (1.0f / 128.0f);

        float sa = 0.0f, sq = 0.0f, sl = 0.0f;
#pragma unroll
        for (int e = 0; e < 16; ++e) {
            const float f = (v[e] < mean) ? 0.0f : v[e];
            const float a = fabsf(f) + 1e-12f;
            sa += a;
            sq  = fmaf(a, a, sq);
            sl  = fmaf(a, __log2f(a), sl);
        }
#pragma unroll
        for (int m = 4; m >= 1; m >>= 1) {
            sa += __shfl_xor_sync(0xffffffffu, sa, m);
            sq += __shfl_xor_sync(0xffffffffu, sq, m);
            sl += __shfl_xor_sync(0xffffffffu, sl, m);
        }
        if (sub == 0) {
            const float nrm = fmaxf(sqrtf(sq), 1e-12f);
            spart[B] = (__log2f(nrm) * sa - sl) / nrm;
        }
    }
    __syncthreads();   // only CTA-wide barrier (cheap: all heavy work done)

    // ---- CTA aggregate + last-CTA finalize (release/acquire ticket) ----
    if (tid == 0) {
        float c0 = 0.0f;
#pragma unroll
        for (int b = 0; b < 32; ++b) c0 += spart[b];
        atomicAdd(&g_acc, (double)c0);              // relaxed device atomic (L2)
        unsigned t;
        asm volatile("atom.add.release.gpu.global.u32 %0, [%1], 1;"
                     : "=r"(t) : "l"(&g_ticket) : "memory");
        if (t == (unsigned)(GRID_DIM - 1)) {        // last CTA: all adds visible
            double v;
            asm volatile("ld.acquire.gpu.global.f64 %0, [%1];"
                         : "=d"(v) : "l"(&g_acc) : "memory");
            out[0] = (float)(v * (1.0 / (double)N_BLOCKS_TOTAL));
            g_acc = 0.0;                            // reset for next replay
            asm volatile("st.release.gpu.global.u32 [%0], 0;"
                         :: "l"(&g_ticket) : "memory");
        }
    }
}

extern "C" void kernel_launch(void* const* d_in, const int* in_sizes, int n_in,
                              void* d_out, int out_size) {
    const float* x = (const float*)d_in[0];
    float* out = (float*)d_out;
    ube_kernel<<<GRID_DIM, 256>>>(x, out);
}